// round 15
// baseline (speedup 1.0000x reference)
#include <cuda_runtime.h>
#include <cuda_bf16.h>
#include <math.h>
#include <stdint.h>

#define N_PTS   29696
#define NZ      32
#define KCLU    100
#define EPSF    1e-5f
#define INDEXF  29696.0f
#define NBLK_PTS 116          // N_PTS / 256
#define NBLK_RE  1856         // (1024/128) * (29696/128)
#define GAP_TAU 1.5e-2f

// ---------------- scratch (static device globals; no allocation) -------------
__device__ __nv_bfloat16 g_xb [(size_t)N_PTS * 1024];
__device__ __nv_bfloat16 g_Pb [(size_t)N_PTS * 2048];   // h3, then d1
__device__ __nv_bfloat16 g_h1b[(size_t)N_PTS * 512];    // h1, then d2
__device__ __nv_bfloat16 g_h2b[(size_t)N_PTS * 512];    // h2, then d3
__device__ __nv_bfloat16 g_zbh[(size_t)N_PTS * NZ];     // z in bf16 (decoder input)
__device__ float g_z [(size_t)N_PTS * NZ];              // z in fp32 (cluster input)
__device__ float g_q [(size_t)N_PTS * KCLU];
__device__ __nv_bfloat16 g_wbt[3712 * 1024];            // transposed bf16 weights
__device__ float g_upart[NBLK_PTS * KCLU];
__device__ float g_Spart[NBLK_PTS];
__device__ float g_klpart[NBLK_PTS];
__device__ float g_repart[NBLK_RE];
__device__ int   g_cnt[KCLU];
__device__ float g_f[KCLU];
__device__ int   g_nflag;
__device__ int   g_flaglist[N_PTS];

// offsets (elements) into g_wbt
#define OFF_WE1 0            // [512][1024]
#define OFF_WE2 (512*1024)   // [512][512]
#define OFF_WE3 (768*1024)   // [2048][512]
#define OFF_WZ  (1792*1024)  // [32][2048]
#define OFF_WD1 (1856*1024)  // [2048][32]
#define OFF_WD2 (1920*1024)  // [512][2048]
#define OFF_WD3 (2944*1024)  // [512][512]
#define OFF_WXB (3200*1024)  // [1024][512]

// ---------------- helpers ------------------------------------------------------
__device__ __forceinline__ uint32_t smem_u32(const void* p) {
    uint32_t a;
    asm("{ .reg .u64 t; cvta.to.shared.u64 t, %1; cvt.u32.u64 %0, t; }" : "=r"(a) : "l"(p));
    return a;
}
__device__ __forceinline__ void cp_async16(uint32_t s, const void* g) {
    asm volatile("cp.async.cg.shared.global [%0], [%1], 16;" :: "r"(s), "l"(g));
}
#define CP_COMMIT() asm volatile("cp.async.commit_group;" ::: "memory")
#define CP_WAIT1()  asm volatile("cp.async.wait_group 1;" ::: "memory")
#define CP_WAIT0()  asm volatile("cp.async.wait_group 0;" ::: "memory")
#define MMA_BF16(c, a, b) \
    asm volatile("mma.sync.aligned.m16n8k16.row.col.f32.bf16.bf16.f32 " \
        "{%0,%1,%2,%3}, {%4,%5,%6,%7}, {%8,%9}, {%0,%1,%2,%3};" \
        : "+f"((c)[0]), "+f"((c)[1]), "+f"((c)[2]), "+f"((c)[3]) \
        : "r"((a)[0]), "r"((a)[1]), "r"((a)[2]), "r"((a)[3]), \
          "r"((b)[0]), "r"((b)[1]))

__global__ void init_kernel() {
    int tid = threadIdx.x;
    if (tid < KCLU) g_cnt[tid] = 0;
    if (tid == 0) g_nflag = 0;
}
__global__ void fill_zero_kernel(float* p, int n) {
    int i = blockIdx.x * blockDim.x + threadIdx.x;
    if (i < n) p[i] = 0.0f;
}
__global__ void conv_bf16_kernel(const float2* __restrict__ in,
                                 __nv_bfloat162* __restrict__ out, int n2) {
    int i = blockIdx.x * blockDim.x + threadIdx.x;
    if (i < n2) {
        float2 v = in[i];
        out[i] = __floats2bfloat162_rn(v.x, v.y);
    }
}
// transpose + convert: W fp32 [K,N] -> Wt bf16 [N,K]; grid(N/32, K/32), block(32,8)
__global__ void tconv_kernel(const float* __restrict__ in, __nv_bfloat16* __restrict__ out,
                             int Kd, int Nd) {
    __shared__ float t[32][33];
    int n0 = blockIdx.x * 32, k0 = blockIdx.y * 32;
    int tx = threadIdx.x, ty = threadIdx.y;
    for (int i = ty; i < 32; i += 8) t[i][tx] = in[(size_t)(k0 + i) * Nd + n0 + tx];
    __syncthreads();
    for (int i = ty; i < 32; i += 8)
        out[(size_t)(n0 + i) * Kd + k0 + tx] = __float2bfloat16_rn(t[tx][i]);
}

// ---------------- bf16 mma.sync GEMM: 512 thr, low-reg, 3-stage cp.async -------
// acc = A[M,K](bf16) @ Wt[N,K](bf16)^T, fp32 accum; + bias, then:
// EPI 0: relu -> bf16. EPI 1: raw fp32 -> Cf AND bf16 -> Cb. EPI 2: sqdiff partials.
// Block 512 thr = 16 warps (4m x 4n); block tile 128 x BN, warp tile 32 x BN/4.
template <int BN, int KB, int EPI>
__global__ void __launch_bounds__(512, 1)
mma_gemm(const __nv_bfloat16* __restrict__ A, const __nv_bfloat16* __restrict__ Bt,
         const float* __restrict__ bias, __nv_bfloat16* __restrict__ Cb,
         float* __restrict__ Cf, const float* __restrict__ X,
         float* __restrict__ part, int N, int K) {
    extern __shared__ char smem[];
    __nv_bfloat16* smh = reinterpret_cast<__nv_bfloat16*>(smem);
    constexpr int LDT = KB + 8;               // halves; pad -> conflict-free
    constexpr int A_TILE_H = 128 * LDT;
    constexpr int B_TILE_H = BN * LDT;
    constexpr int STAGE_H = A_TILE_H + B_TILE_H;
    constexpr int NTL = BN / 32;              // 8-col subtiles per warp
    constexpr int WN = BN / 4;                // warp n extent
    constexpr int CPR = KB / 8;               // 16B chunks per row
    constexpr int A_IT = (128 * CPR + 511) / 512;
    constexpr int B_IT = (BN * CPR + 511) / 512;

    const int tid = threadIdx.x;
    const int wid = tid >> 5;
    const int lane = tid & 31;
    const int g = lane >> 2;
    const int t = lane & 3;
    const int warp_m = wid >> 2;              // 0..3 -> 32 rows each
    const int warp_n = wid & 3;               // 0..3 -> WN cols each
    const int bm = blockIdx.y * 128, bn = blockIdx.x * BN;
    const uint32_t sb = smem_u32(smh);

    float acc[2][NTL][4];
#pragma unroll
    for (int mt = 0; mt < 2; mt++)
#pragma unroll
        for (int nt = 0; nt < NTL; nt++)
#pragma unroll
            for (int i = 0; i < 4; i++) acc[mt][nt][i] = 0.0f;

    const int NC = K / KB;

    auto prefetch = [&](int c, int s) {
        const int k0 = c * KB;
        const uint32_t base = sb + (uint32_t)s * STAGE_H * 2;
#pragma unroll
        for (int i = 0; i < A_IT; i++) {
            int idx = tid + i * 512;
            if ((128 * CPR) % 512 == 0 || idx < 128 * CPR) {
                int r = idx / CPR, ch = idx % CPR;
                cp_async16(base + (r * LDT + ch * 8) * 2,
                           &A[(size_t)(bm + r) * K + k0 + ch * 8]);
            }
        }
#pragma unroll
        for (int i = 0; i < B_IT; i++) {
            int idx = tid + i * 512;
            if ((BN * CPR) % 512 == 0 || idx < BN * CPR) {
                int r = idx / CPR, ch = idx % CPR;
                cp_async16(base + (A_TILE_H + r * LDT + ch * 8) * 2,
                           &Bt[(size_t)(bn + r) * K + k0 + ch * 8]);
            }
        }
    };

    auto compute = [&](int s) {
        const __nv_bfloat16* As = smh + s * STAGE_H;
        const __nv_bfloat16* Bs = As + A_TILE_H;
#pragma unroll
        for (int s16 = 0; s16 < KB / 16; s16++) {
            const int kb = s16 * 16 + 2 * t;
            uint32_t bf[NTL][2];
#pragma unroll
            for (int nt = 0; nt < NTL; nt++) {
                int nb = warp_n * WN + nt * 8 + g;
                bf[nt][0] = *reinterpret_cast<const uint32_t*>(&Bs[nb * LDT + kb]);
                bf[nt][1] = *reinterpret_cast<const uint32_t*>(&Bs[nb * LDT + kb + 8]);
            }
#pragma unroll
            for (int mt = 0; mt < 2; mt++) {
                int mb = warp_m * 32 + mt * 16 + g;
                uint32_t af[4];
                af[0] = *reinterpret_cast<const uint32_t*>(&As[mb * LDT + kb]);
                af[1] = *reinterpret_cast<const uint32_t*>(&As[(mb + 8) * LDT + kb]);
                af[2] = *reinterpret_cast<const uint32_t*>(&As[mb * LDT + kb + 8]);
                af[3] = *reinterpret_cast<const uint32_t*>(&As[(mb + 8) * LDT + kb + 8]);
#pragma unroll
                for (int nt = 0; nt < NTL; nt++) MMA_BF16(acc[mt][nt], af, bf[nt]);
            }
        }
    };

    // ---- 3-stage pipelined mainloop, single sync per iteration ----
    prefetch(0, 0);
    CP_COMMIT();
    if (NC > 1) { prefetch(1, 1); CP_COMMIT(); }
#pragma unroll 1
    for (int c = 0; c < NC; c++) {
        if (c + 1 < NC) CP_WAIT1(); else CP_WAIT0();
        __syncthreads();          // group c landed; all warps done reading stage (c+2)%3
        if (c + 2 < NC) { prefetch(c + 2, (c + 2) % 3); CP_COMMIT(); }
        compute(c % 3);
    }

    // ---- epilogue straight from accumulators ----
    float lsum = 0.0f;
#pragma unroll
    for (int mt = 0; mt < 2; mt++) {
#pragma unroll
        for (int nt = 0; nt < NTL; nt++) {
            int row = bm + warp_m * 32 + mt * 16 + g;
            int col = bn + warp_n * WN + nt * 8 + 2 * t;
            float b0 = bias[col], b1 = bias[col + 1];
            float v0 = acc[mt][nt][0] + b0, v1 = acc[mt][nt][1] + b1;
            float v2 = acc[mt][nt][2] + b0, v3 = acc[mt][nt][3] + b1;
            size_t i0 = (size_t)row * N + col;
            size_t i1 = (size_t)(row + 8) * N + col;
            if (EPI == 0) {
                v0 = fmaxf(v0, 0.0f); v1 = fmaxf(v1, 0.0f);
                v2 = fmaxf(v2, 0.0f); v3 = fmaxf(v3, 0.0f);
                *reinterpret_cast<__nv_bfloat162*>(&Cb[i0]) = __floats2bfloat162_rn(v0, v1);
                *reinterpret_cast<__nv_bfloat162*>(&Cb[i1]) = __floats2bfloat162_rn(v2, v3);
            } else if (EPI == 1) {
                *reinterpret_cast<float2*>(&Cf[i0]) = make_float2(v0, v1);
                *reinterpret_cast<float2*>(&Cf[i1]) = make_float2(v2, v3);
                *reinterpret_cast<__nv_bfloat162*>(&Cb[i0]) = __floats2bfloat162_rn(v0, v1);
                *reinterpret_cast<__nv_bfloat162*>(&Cb[i1]) = __floats2bfloat162_rn(v2, v3);
            } else {
                float2 x0 = *reinterpret_cast<const float2*>(&X[i0]);
                float2 x1 = *reinterpret_cast<const float2*>(&X[i1]);
                float d0 = v0 - x0.x, d1 = v1 - x0.y, d2 = v2 - x1.x, d3 = v3 - x1.y;
                lsum += d0 * d0 + d1 * d1 + d2 * d2 + d3 * d3;
            }
        }
    }
    if (EPI == 2) {
        __syncthreads();
        float* red = reinterpret_cast<float*>(smem);
        red[tid] = lsum;
        __syncthreads();
        for (int s2 = 256; s2 > 0; s2 >>= 1) {
            if (tid < s2) red[tid] += red[tid + s2];
            __syncthreads();
        }
        if (tid == 0) part[blockIdx.y * gridDim.x + blockIdx.x] = red[0];
    }
}

// ---------------- clustering pass A -------------------------------------------
__global__ void cluster_pass(const float* __restrict__ t1,
                             const float* __restrict__ clu,
                             float* __restrict__ out_predict) {
    __shared__ float cs[KCLU * NZ];
    __shared__ float u_s[KCLU];
    __shared__ float red[256];
    int tid = threadIdx.x;
    for (int i = tid; i < KCLU * NZ; i += 256) cs[i] = clu[i];
    if (tid < KCLU) u_s[tid] = 0.0f;
    __syncthreads();

    int p = blockIdx.x * 256 + tid;
    float zr[NZ];
    const float* zp = g_z + (size_t)p * NZ;
#pragma unroll
    for (int i = 0; i < NZ; i++) zr[i] = zp[i];

    float cm = (t1[p * 3 + 0] * 0.01f) * (t1[p * 3 + 1] * 0.01f) * (t1[p * 3 + 2] * 0.01f)
               * 0.99f + 1.0f;
    float s = 0.0f;
#pragma unroll
    for (int i = 0; i < NZ; i++) { zr[i] *= cm; s += zr[i]; }
    float mean = s * (1.0f / NZ);
    float var = 0.0f;
#pragma unroll
    for (int i = 0; i < NZ; i++) { float d = zr[i] - mean; var += d * d; }
    float isd = 1.0f / sqrtf(var * (1.0f / (NZ - 1)));
#pragma unroll
    for (int i = 0; i < NZ; i++) zr[i] = (zr[i] - mean) * isd;

    float sumq = 0.0f, best = -1.0f, best2 = -1.0f;
    int bi = 0;
    for (int j = 0; j < KCLU; j++) {
        const float* c = &cs[j * NZ];
        float d = 0.0f;
#pragma unroll
        for (int i = 0; i < NZ; i++) { float tt = zr[i] - c[i]; d += tt * tt; }
        float qu = EPSF + d;
        sumq += qu;
        if (qu > best) { best2 = best; best = qu; bi = j; }
        else if (qu > best2) best2 = qu;
    }
    out_predict[p] = (float)bi;
    atomicAdd(&g_cnt[bi], 1);
    if (best - best2 < GAP_TAU * best) {       // near-tie: flag for fp32 rescue
        int ii = atomicAdd(&g_nflag, 1);
        g_flaglist[ii] = p;
    }

    float inv = 1.0f / sumq;
    float Sl = 0.0f;
    float* qrow = g_q + (size_t)p * KCLU;
    for (int j = 0; j < KCLU; j++) {
        const float* c = &cs[j * NZ];
        float d = 0.0f;
#pragma unroll
        for (int i = 0; i < NZ; i++) { float tt = zr[i] - c[i]; d += tt * tt; }
        float qn = (EPSF + d) * inv;
        qrow[j] = qn;
        atomicAdd(&u_s[j], qn);
        float lq = logf(qn);
        float tq = (1.0f - qn) * (1.0f - qn) * lq * INDEXF;
        Sl += sqrtf(-1.0f / tq);
    }

    red[tid] = Sl;
    __syncthreads();
    for (int s2 = 128; s2 > 0; s2 >>= 1) {
        if (tid < s2) red[tid] += red[tid + s2];
        __syncthreads();
    }
    if (tid == 0) g_Spart[blockIdx.x] = red[0];
    __syncthreads();
    if (tid < KCLU) g_upart[blockIdx.x * KCLU + tid] = u_s[tid];
}

// ---------------- fp32 rescue for near-tie points ------------------------------
#define RB 8
__global__ void __launch_bounds__(256, 1)
rescue_kernel(const float* __restrict__ x, const float* __restrict__ t1,
              const float* __restrict__ clu,
              const float* __restrict__ We1, const float* __restrict__ be1,
              const float* __restrict__ We2, const float* __restrict__ be2,
              const float* __restrict__ We3, const float* __restrict__ be3,
              const float* __restrict__ Wz,  const float* __restrict__ bz,
              float* __restrict__ out_predict) {
    extern __shared__ float sm[];
    float* xb  = sm;                  // [1024][RB]
    float* hh  = xb + RB * 1024;      // [2048][RB]
    float* s1b = hh + RB * 2048;      // [512][RB]
    float* s2b = s1b + RB * 512;      // [512][RB]
    float* zz  = s2b + RB * 512;      // [RB][32]
    float* pz  = zz + RB * 32;        // [8][32][RB]
    float* dst = pz + 8 * 32 * RB;    // [128]
    const int tid = threadIdx.x;
    const int nf = g_nflag;

    for (int base = blockIdx.x * RB; base < nf; base += gridDim.x * RB) {
        const int cb = min(RB, nf - base);
        int plist[RB];
#pragma unroll
        for (int i = 0; i < RB; i++) plist[i] = g_flaglist[base + (i < cb ? i : 0)];
        __syncthreads();
        for (int k = tid; k < 1024; k += 256) {
#pragma unroll
            for (int i = 0; i < RB; i++)
                xb[k * RB + i] = x[(size_t)plist[i] * 1024 + k];
        }
        __syncthreads();
        for (int n = tid; n < 512; n += 256) {
            float acc[RB] = {};
            for (int k = 0; k < 1024; k++) {
                float w = We1[(size_t)k * 512 + n];
                float4 v0 = *reinterpret_cast<const float4*>(&xb[k * RB]);
                float4 v1 = *reinterpret_cast<const float4*>(&xb[k * RB + 4]);
                acc[0] += v0.x * w; acc[1] += v0.y * w; acc[2] += v0.z * w; acc[3] += v0.w * w;
                acc[4] += v1.x * w; acc[5] += v1.y * w; acc[6] += v1.z * w; acc[7] += v1.w * w;
            }
            float b = be1[n];
#pragma unroll
            for (int i = 0; i < RB; i++) s1b[n * RB + i] = fmaxf(acc[i] + b, 0.0f);
        }
        __syncthreads();
        for (int n = tid; n < 512; n += 256) {
            float acc[RB] = {};
            for (int k = 0; k < 512; k++) {
                float w = We2[(size_t)k * 512 + n];
                float4 v0 = *reinterpret_cast<const float4*>(&s1b[k * RB]);
                float4 v1 = *reinterpret_cast<const float4*>(&s1b[k * RB + 4]);
                acc[0] += v0.x * w; acc[1] += v0.y * w; acc[2] += v0.z * w; acc[3] += v0.w * w;
                acc[4] += v1.x * w; acc[5] += v1.y * w; acc[6] += v1.z * w; acc[7] += v1.w * w;
            }
            float b = be2[n];
#pragma unroll
            for (int i = 0; i < RB; i++) s2b[n * RB + i] = fmaxf(acc[i] + b, 0.0f);
        }
        __syncthreads();
        for (int n = tid; n < 2048; n += 256) {
            float acc[RB] = {};
            for (int k = 0; k < 512; k++) {
                float w = We3[(size_t)k * 2048 + n];
                float4 v0 = *reinterpret_cast<const float4*>(&s2b[k * RB]);
                float4 v1 = *reinterpret_cast<const float4*>(&s2b[k * RB + 4]);
                acc[0] += v0.x * w; acc[1] += v0.y * w; acc[2] += v0.z * w; acc[3] += v0.w * w;
                acc[4] += v1.x * w; acc[5] += v1.y * w; acc[6] += v1.z * w; acc[7] += v1.w * w;
            }
            float b = be3[n];
#pragma unroll
            for (int i = 0; i < RB; i++) hh[n * RB + i] = fmaxf(acc[i] + b, 0.0f);
        }
        __syncthreads();
        {
            int n = tid & 31, kc = tid >> 5;
            float acc[RB] = {};
            for (int k = kc * 256; k < kc * 256 + 256; k++) {
                float w = Wz[(size_t)k * 32 + n];
                float4 v0 = *reinterpret_cast<const float4*>(&hh[k * RB]);
                float4 v1 = *reinterpret_cast<const float4*>(&hh[k * RB + 4]);
                acc[0] += v0.x * w; acc[1] += v0.y * w; acc[2] += v0.z * w; acc[3] += v0.w * w;
                acc[4] += v1.x * w; acc[5] += v1.y * w; acc[6] += v1.z * w; acc[7] += v1.w * w;
            }
#pragma unroll
            for (int i = 0; i < RB; i++) pz[(kc * 32 + n) * RB + i] = acc[i];
        }
        __syncthreads();
        if (tid < 32) {
            int n = tid;
            float b = bz[n];
#pragma unroll
            for (int i = 0; i < RB; i++) {
                float s = 0.0f;
                for (int kc = 0; kc < 8; kc++) s += pz[(kc * 32 + n) * RB + i];
                zz[i * 32 + n] = s + b;
            }
        }
        __syncthreads();
        if (tid < cb) {
            int i = tid;
            int p = plist[i];
            float cm = (t1[p * 3 + 0] * 0.01f) * (t1[p * 3 + 1] * 0.01f) *
                       (t1[p * 3 + 2] * 0.01f) * 0.99f + 1.0f;
            float s = 0.0f;
            for (int k = 0; k < NZ; k++) { zz[i * 32 + k] *= cm; s += zz[i * 32 + k]; }
            float mean = s * (1.0f / NZ);
            float var = 0.0f;
            for (int k = 0; k < NZ; k++) { float d = zz[i * 32 + k] - mean; var += d * d; }
            float isd = 1.0f / sqrtf(var * (1.0f / (NZ - 1)));
            for (int k = 0; k < NZ; k++) zz[i * 32 + k] = (zz[i * 32 + k] - mean) * isd;
        }
        __syncthreads();
        for (int i = 0; i < cb; i++) {
            if (tid < KCLU) {
                float d = 0.0f;
                for (int k = 0; k < NZ; k++) {
                    float tt = zz[i * 32 + k] - clu[tid * NZ + k];
                    d += tt * tt;
                }
                dst[tid] = d;
            }
            __syncthreads();
            if (tid == 0) {
                float best = -1.0f; int bi = 0;
                for (int j = 0; j < KCLU; j++)
                    if (dst[j] > best) { best = dst[j]; bi = j; }
                int p = plist[i];
                int old = (int)out_predict[p];
                if (old != bi) {
                    atomicAdd(&g_cnt[old], -1);
                    atomicAdd(&g_cnt[bi], 1);
                    out_predict[p] = (float)bi;
                }
            }
            __syncthreads();
        }
    }
}

// ---------------- stats pass B -------------------------------------------------
__global__ void stats_kernel() {
    __shared__ float u[KCLU];
    __shared__ float sred[128];
    int tid = threadIdx.x;
    if (tid < KCLU) {
        float s = 0.0f;
        for (int b = 0; b < NBLK_PTS; b++) s += g_upart[b * KCLU + tid];
        u[tid] = s;
    }
    float sp = (tid < NBLK_PTS) ? g_Spart[tid] : 0.0f;
    sred[tid] = sp;
    __syncthreads();
    for (int s = 64; s > 0; s >>= 1) {
        if (tid < s) sred[tid] += sred[tid + s];
        __syncthreads();
    }
    if (tid == 0) {
        float S = sred[0];
        float um = 0.0f;
        for (int j = 0; j < KCLU; j++) um += u[j];
        um /= KCLU;
        float uv = 0.0f;
        for (int j = 0; j < KCLU; j++) { float d = u[j] - um; uv += d * d; }
        float usd = sqrtf(uv / (KCLU - 1));

        float v[KCLU];
        float vm = 0.0f;
        for (int j = 0; j < KCLU; j++) {
            int c = g_cnt[j]; if (c < 1) c = 1;
            v[j] = sqrtf((float)c) * S;
            vm += v[j];
        }
        vm /= KCLU;
        float vv = 0.0f;
        for (int j = 0; j < KCLU; j++) { float d = v[j] - vm; vv += d * d; }
        float vsd = sqrtf(vv / (KCLU - 1));

        float umin = 1e30f, vmin = 1e30f;
        for (int j = 0; j < KCLU; j++) {
            float un = (u[j] - um) / usd;
            float vn = (v[j] - vm) / vsd;
            u[j] = un; v[j] = vn;
            if (un < umin) umin = un;
            if (vn < vmin) vmin = vn;
        }
        for (int j = 0; j < KCLU; j++)
            g_f[j] = (u[j] - umin + 0.001f) + (v[j] - vmin + 0.001f) + 1.0f;
    }
}

// ---------------- KL pass C -----------------------------------------------------
__global__ void kl_pass() {
    __shared__ float fs[KCLU];
    __shared__ float red[256];
    int tid = threadIdx.x;
    if (tid < KCLU) fs[tid] = g_f[tid];
    __syncthreads();
    int p = blockIdx.x * 256 + tid;
    const float* qrow = g_q + (size_t)p * KCLU;
    float sw = 0.0f;
    for (int j = 0; j < KCLU; j++) { float q = qrow[j]; sw += q * q / fs[j]; }
    float inv = 1.0f / sw;
    float kl = 0.0f;
    for (int j = 0; j < KCLU; j++) {
        float q = qrow[j];
        float pj = q * q / fs[j] * inv;
        kl += pj * (logf(pj) - logf(q));
    }
    red[tid] = kl;
    __syncthreads();
    for (int s2 = 128; s2 > 0; s2 >>= 1) {
        if (tid < s2) red[tid] += red[tid + s2];
        __syncthreads();
    }
    if (tid == 0) g_klpart[blockIdx.x] = red[0];
}

// ---------------- final loss ----------------------------------------------------
__global__ void final_kernel(const float* __restrict__ clu, float* __restrict__ out) {
    __shared__ float red[256];
    int tid = threadIdx.x;
    float kl = 0.0f;
    for (int i = tid; i < NBLK_PTS; i += 256) kl += g_klpart[i];
    float re = 0.0f;
    for (int i = tid; i < NBLK_RE; i += 256) re += g_repart[i];
    float D = 0.0f;
    for (int idx = tid; idx < KCLU * KCLU; idx += 256) {
        int i = idx / KCLU, j = idx % KCLU;
        float d = 0.0f;
        for (int kk = 0; kk < NZ; kk++) {
            float t = clu[i * NZ + kk] - clu[j * NZ + kk];
            d += t * t;
        }
        D += d;
    }
    red[tid] = kl; __syncthreads();
    for (int s = 128; s > 0; s >>= 1) { if (tid < s) red[tid] += red[tid + s]; __syncthreads(); }
    float kls = red[0]; __syncthreads();
    red[tid] = re; __syncthreads();
    for (int s = 128; s > 0; s >>= 1) { if (tid < s) red[tid] += red[tid + s]; __syncthreads(); }
    float res = red[0]; __syncthreads();
    red[tid] = D; __syncthreads();
    for (int s = 128; s > 0; s >>= 1) { if (tid < s) red[tid] += red[tid + s]; __syncthreads(); }
    if (tid == 0) {
        float kl_loss = 0.01f * kls / ((float)N_PTS * (float)KCLU);
        float re_loss = res / ((float)N_PTS * 1024.0f);
        float mean_d = red[0] / (float)(KCLU * KCLU - KCLU);
        out[N_PTS] = kl_loss + re_loss + 0.01f / mean_d;
    }
}

// ---------------- host ----------------------------------------------------------
extern "C" void kernel_launch(void* const* d_in, const int* in_sizes, int n_in,
                              void* d_out, int out_size) {
    const float* x   = (const float*)d_in[0];
    const float* t1  = (const float*)d_in[1];
    const float* clu = (const float*)d_in[2];
    const float* We1 = (const float*)d_in[3];  const float* be1 = (const float*)d_in[4];
    const float* We2 = (const float*)d_in[5];  const float* be2 = (const float*)d_in[6];
    const float* We3 = (const float*)d_in[7];  const float* be3 = (const float*)d_in[8];
    const float* Wz  = (const float*)d_in[9];  const float* bz  = (const float*)d_in[10];
    const float* Wd1 = (const float*)d_in[11]; const float* bd1 = (const float*)d_in[12];
    const float* Wd2 = (const float*)d_in[13]; const float* bd2 = (const float*)d_in[14];
    const float* Wd3 = (const float*)d_in[15]; const float* bd3 = (const float*)d_in[16];
    const float* Wxb = (const float*)d_in[17]; const float* bxb = (const float*)d_in[18];
    float* out = (float*)d_out;

    __nv_bfloat16 *xb, *Pb, *h1b, *h2b, *zbh, *wbt;
    float *zf, *repart;
    cudaGetSymbolAddress((void**)&xb,  g_xb);
    cudaGetSymbolAddress((void**)&Pb,  g_Pb);
    cudaGetSymbolAddress((void**)&h1b, g_h1b);
    cudaGetSymbolAddress((void**)&h2b, g_h2b);
    cudaGetSymbolAddress((void**)&zbh, g_zbh);
    cudaGetSymbolAddress((void**)&wbt, g_wbt);
    cudaGetSymbolAddress((void**)&zf,  g_z);
    cudaGetSymbolAddress((void**)&repart, g_repart);

    constexpr int SM_128 = (128 * 72 + 128 * 72) * 2 * 3;   // 110592 B (KB=64)
    constexpr int SM_32  = (128 * 72 + 32 * 72) * 2 * 3;    //  69120 B (BN=32,KB=64)
    constexpr int SM_D1  = (128 * 40 + 128 * 40) * 2 * 3;   //  61440 B (KB=32)
    constexpr int SM_RES = (RB * 1024 + RB * 2048 + RB * 512 + RB * 512 + RB * 32
                            + 8 * 32 * RB + 128) * 4;
    cudaFuncSetAttribute(mma_gemm<128, 64, 0>, cudaFuncAttributeMaxDynamicSharedMemorySize, SM_128);
    cudaFuncSetAttribute(mma_gemm<32, 64, 1>,  cudaFuncAttributeMaxDynamicSharedMemorySize, SM_32);
    cudaFuncSetAttribute(mma_gemm<128, 32, 0>, cudaFuncAttributeMaxDynamicSharedMemorySize, SM_D1);
    cudaFuncSetAttribute(mma_gemm<128, 64, 2>, cudaFuncAttributeMaxDynamicSharedMemorySize, SM_128);
    cudaFuncSetAttribute(rescue_kernel, cudaFuncAttributeMaxDynamicSharedMemorySize, SM_RES);

    init_kernel<<<1, 128>>>();

    // prep: x -> bf16; weights -> transposed bf16 [N,K]
    {
        int n2 = N_PTS * 1024 / 2;
        conv_bf16_kernel<<<(n2 + 255) / 256, 256>>>((const float2*)x, (__nv_bfloat162*)xb, n2);
    }
    dim3 tb(32, 8);
    tconv_kernel<<<dim3(512 / 32, 1024 / 32), tb>>>(We1, wbt + OFF_WE1, 1024, 512);
    tconv_kernel<<<dim3(512 / 32, 512 / 32), tb>>>(We2, wbt + OFF_WE2, 512, 512);
    tconv_kernel<<<dim3(2048 / 32, 512 / 32), tb>>>(We3, wbt + OFF_WE3, 512, 2048);
    tconv_kernel<<<dim3(1, 2048 / 32), tb>>>(Wz, wbt + OFF_WZ, 2048, 32);
    tconv_kernel<<<dim3(2048 / 32, 1), tb>>>(Wd1, wbt + OFF_WD1, 32, 2048);
    tconv_kernel<<<dim3(512 / 32, 2048 / 32), tb>>>(Wd2, wbt + OFF_WD2, 2048, 512);
    tconv_kernel<<<dim3(512 / 32, 512 / 32), tb>>>(Wd3, wbt + OFF_WD3, 512, 512);
    tconv_kernel<<<dim3(1024 / 32, 512 / 32), tb>>>(Wxb, wbt + OFF_WXB, 512, 1024);

    const dim3 blk(512);
    const int MB = N_PTS / 128;  // 232

    // encoder
    mma_gemm<128, 64, 0><<<dim3(4, MB), blk, SM_128>>>(xb, wbt + OFF_WE1, be1, h1b, nullptr, nullptr, nullptr, 512, 1024);
    mma_gemm<128, 64, 0><<<dim3(4, MB), blk, SM_128>>>(h1b, wbt + OFF_WE2, be2, h2b, nullptr, nullptr, nullptr, 512, 512);
    mma_gemm<128, 64, 0><<<dim3(16, MB), blk, SM_128>>>(h2b, wbt + OFF_WE3, be3, Pb, nullptr, nullptr, nullptr, 2048, 512);
    mma_gemm<32, 64, 1><<<dim3(1, MB), blk, SM_32>>>(Pb, wbt + OFF_WZ, bz, zbh, zf, nullptr, nullptr, 32, 2048);
    // decoder
    mma_gemm<128, 32, 0><<<dim3(16, MB), blk, SM_D1>>>(zbh, wbt + OFF_WD1, bd1, Pb, nullptr, nullptr, nullptr, 2048, 32);
    mma_gemm<128, 64, 0><<<dim3(4, MB), blk, SM_128>>>(Pb, wbt + OFF_WD2, bd2, h1b, nullptr, nullptr, nullptr, 512, 2048);
    mma_gemm<128, 64, 0><<<dim3(4, MB), blk, SM_128>>>(h1b, wbt + OFF_WD3, bd3, h2b, nullptr, nullptr, nullptr, 512, 512);
    mma_gemm<128, 64, 2><<<dim3(8, MB), blk, SM_128>>>(h2b, wbt + OFF_WXB, bxb, nullptr, nullptr, x, repart, 1024, 512);

    // clustering + rescue + loss
    cluster_pass<<<NBLK_PTS, 256>>>(t1, clu, out);
    rescue_kernel<<<148, 256, SM_RES>>>(x, t1, clu, We1, be1, We2, be2, We3, be3, Wz, bz, out);
    stats_kernel<<<1, 128>>>();
    kl_pass<<<NBLK_PTS, 256>>>();
    final_kernel<<<1, 256>>>(clu, out);

    int extra = out_size - (N_PTS + 1);
    if (extra > 0) fill_zero_kernel<<<(extra + 255) / 256, 256>>>(out + N_PTS + 1, extra);
}

// round 17
// speedup vs baseline: 1.1197x; 1.1197x over previous
#include <cuda_runtime.h>
#include <cuda_bf16.h>
#include <math.h>
#include <stdint.h>

#define N_PTS   29696
#define NZ      32
#define KCLU    100
#define EPSF    1e-5f
#define INDEXF  29696.0f
#define NBLK_PTS 116          // N_PTS / 256
#define NBLK_RE  1856         // (1024/128) * (29696/128)
#define GAP_TAU 5e-3f

// ---------------- scratch (static device globals; no allocation) -------------
__device__ float g_P [(size_t)N_PTS * 2048];            // h3 (encoder, fp32)
__device__ float g_h1[(size_t)N_PTS * 512];
__device__ float g_h2[(size_t)N_PTS * 512];
__device__ float g_z [(size_t)N_PTS * NZ];              // z fp32 (cluster input)
__device__ __nv_bfloat16 g_zbh[(size_t)N_PTS * NZ];     // z bf16 (decoder input)
__device__ __nv_bfloat16 g_d1b[(size_t)N_PTS * 2048];   // decoder acts (bf16)
__device__ __nv_bfloat16 g_d2b[(size_t)N_PTS * 512];
__device__ __nv_bfloat16 g_d3b[(size_t)N_PTS * 512];
__device__ float g_q [(size_t)N_PTS * KCLU];
__device__ float g_wr[3712 * 1024];                     // pre-rounded tf32 weights
__device__ float g_upart[NBLK_PTS * KCLU];
__device__ float g_Spart[NBLK_PTS];
__device__ float g_klpart[NBLK_PTS];
__device__ float g_repart[NBLK_RE];
__device__ int   g_cnt[KCLU];
__device__ float g_f[KCLU];
__device__ int   g_nflag;
__device__ int   g_flaglist[N_PTS];

// offsets (floats) into g_wr
#define OFF_WE1 0            // 1024*512
#define OFF_WE2 (512*1024)
#define OFF_WE3 (768*1024)
#define OFF_WZ  (1792*1024)
#define OFF_WD1 (1856*1024)
#define OFF_WD2 (1920*1024)
#define OFF_WD3 (2944*1024)
#define OFF_WXB (3200*1024)

// ---------------- helpers ------------------------------------------------------
__device__ __forceinline__ float tf32_rna(float x) {
    uint32_t u;
    asm("cvt.rna.tf32.f32 %0, %1;" : "=r"(u) : "f"(x));
    return __uint_as_float(u);
}
__device__ __forceinline__ uint32_t smem_u32(const void* p) {
    uint32_t a;
    asm("{ .reg .u64 t; cvta.to.shared.u64 t, %1; cvt.u32.u64 %0, t; }" : "=r"(a) : "l"(p));
    return a;
}
__device__ __forceinline__ void cp_async16(uint32_t s, const void* g) {
    asm volatile("cp.async.cg.shared.global [%0], [%1], 16;" :: "r"(s), "l"(g));
}
#define CP_COMMIT() asm volatile("cp.async.commit_group;" ::: "memory")
#define CP_WAIT1()  asm volatile("cp.async.wait_group 1;" ::: "memory")
#define CP_WAIT0()  asm volatile("cp.async.wait_group 0;" ::: "memory")
#define MMA_TF32(c, a, b) \
    asm volatile("mma.sync.aligned.m16n8k8.row.col.f32.tf32.tf32.f32 " \
        "{%0,%1,%2,%3}, {%4,%5,%6,%7}, {%8,%9}, {%0,%1,%2,%3};" \
        : "+f"((c)[0]), "+f"((c)[1]), "+f"((c)[2]), "+f"((c)[3]) \
        : "r"((a)[0]), "r"((a)[1]), "r"((a)[2]), "r"((a)[3]), \
          "r"((b)[0]), "r"((b)[1]))

__global__ void init_kernel() {
    int tid = threadIdx.x;
    if (tid < KCLU) g_cnt[tid] = 0;
    if (tid == 0) g_nflag = 0;
}
__global__ void fill_zero_kernel(float* p, int n) {
    int i = blockIdx.x * blockDim.x + threadIdx.x;
    if (i < n) p[i] = 0.0f;
}
__global__ void round4_kernel(const float4* __restrict__ in, float4* __restrict__ out, int n4) {
    int i = blockIdx.x * blockDim.x + threadIdx.x;
    if (i < n4) {
        float4 v = in[i];
        v.x = tf32_rna(v.x); v.y = tf32_rna(v.y);
        v.z = tf32_rna(v.z); v.w = tf32_rna(v.w);
        out[i] = v;
    }
}

// ---------------- tf32 mma.sync GEMM (cp.async, swizzled A, pre-rounded W) -----
// C = epi(A[M,K] @ W[K,N] + bias). W pre-rounded tf32 fp32 [K,N].
// ABF: 0 -> A raw fp32 (cvt in regs); 1 -> A fp32 already tf32-rounded;
//      2 -> A bf16 (widen in regs; exact tf32 subset).
// EPI: 0 relu+round -> fp32 Cf.  1 raw fp32 -> Cf AND bf16 -> Cb.
//      2 fused sum((v-X)^2) partials.  3 relu -> bf16 Cb.
template <int BN, int ABF, int EPI>
__global__ void __launch_bounds__(256, 2)
mma_gemm(const void* __restrict__ Av, const float* __restrict__ W,
         const float* __restrict__ bias, float* __restrict__ Cf,
         __nv_bfloat16* __restrict__ Cb, const float* __restrict__ X,
         float* __restrict__ part, int N, int K) {
    extern __shared__ char smem[];
    constexpr int A_TILE_B = (ABF == 2) ? 128 * 40 * 2 : 128 * 32 * 4;
    constexpr int LDB = BN + 8;
    constexpr int B_TILE_B = 32 * LDB * 4;
    constexpr int STAGE_B = A_TILE_B + B_TILE_B;
    constexpr int NTL = BN / 32;
    constexpr int WN = BN / 4;
    constexpr int BNC = BN / 4;
    constexpr int B_CP = (32 * BNC) / 256;

    const int tid = threadIdx.x;
    const int lane = tid & 31;
    const int wid = tid >> 5;
    const int g = lane >> 2;
    const int t = lane & 3;
    const int warp_m = wid >> 2;
    const int warp_n = wid & 3;
    const int bm = blockIdx.y * 128, bn = blockIdx.x * BN;
    const uint32_t sb = smem_u32(smem);

    float acc[4][NTL][4];
#pragma unroll
    for (int mt = 0; mt < 4; mt++)
#pragma unroll
        for (int nt = 0; nt < NTL; nt++)
#pragma unroll
            for (int i = 0; i < 4; i++) acc[mt][nt][i] = 0.0f;

    const int NC = K >> 5;

    auto prefetch = [&](int c, int s) {
        const int k0 = c << 5;
        const uint32_t base = sb + (uint32_t)s * STAGE_B;
        if (ABF == 2) {
            const __nv_bfloat16* A = (const __nv_bfloat16*)Av;
#pragma unroll
            for (int i = 0; i < 2; i++) {                   // 512 chunks of 8 halves
                int idx = tid + i * 256;
                int r = idx >> 2, ch = idx & 3;
                cp_async16(base + (r * 40 + ch * 8) * 2,
                           &A[(size_t)(bm + r) * K + k0 + ch * 8]);
            }
        } else {
            const float* A = (const float*)Av;
#pragma unroll
            for (int i = 0; i < 4; i++) {                   // 1024 chunks of 4 floats
                int idx = tid + i * 256;
                int r = idx >> 3, c4 = idx & 7;
                int c4s = c4 ^ (r & 7);                     // XOR swizzle
                cp_async16(base + (r * 32 + c4s * 4) * 4,
                           &A[(size_t)(bm + r) * K + k0 + c4 * 4]);
            }
        }
#pragma unroll
        for (int i = 0; i < B_CP; i++) {
            int idx = tid + i * 256;
            int r = idx / BNC, c4 = idx % BNC;
            cp_async16(base + A_TILE_B + (r * LDB + c4 * 4) * 4,
                       &W[(size_t)(k0 + r) * N + bn + c4 * 4]);
        }
    };

    auto compute = [&](int s) {
        const float* Bs = (const float*)(smem + s * STAGE_B + A_TILE_B);
#pragma unroll
        for (int ks = 0; ks < 4; ks++) {
            const int kk = ks * 8 + t;
            const int c0 = 2 * ks, c1 = 2 * ks + 1;
            uint32_t bh[NTL][2];
#pragma unroll
            for (int nt = 0; nt < NTL; nt++) {
                int nb = warp_n * WN + nt * 8 + g;
                bh[nt][0] = __float_as_uint(Bs[kk * LDB + nb]);
                bh[nt][1] = __float_as_uint(Bs[(kk + 4) * LDB + nb]);
            }
#pragma unroll
            for (int mt = 0; mt < 4; mt++) {
                int r0 = warp_m * 64 + mt * 16 + g;
                float a0, a1, a2, a3;
                if (ABF == 2) {
                    const __nv_bfloat16* As = (const __nv_bfloat16*)(smem + s * STAGE_B);
                    a0 = __bfloat162float(As[r0 * 40 + kk]);
                    a1 = __bfloat162float(As[(r0 + 8) * 40 + kk]);
                    a2 = __bfloat162float(As[r0 * 40 + kk + 4]);
                    a3 = __bfloat162float(As[(r0 + 8) * 40 + kk + 4]);
                } else {
                    const float* As = (const float*)(smem + s * STAGE_B);
                    a0 = As[r0 * 32 + ((c0 ^ g) << 2) + t];
                    a1 = As[(r0 + 8) * 32 + ((c0 ^ g) << 2) + t];
                    a2 = As[r0 * 32 + ((c1 ^ g) << 2) + t];
                    a3 = As[(r0 + 8) * 32 + ((c1 ^ g) << 2) + t];
                    if (ABF == 0) {
                        a0 = tf32_rna(a0); a1 = tf32_rna(a1);
                        a2 = tf32_rna(a2); a3 = tf32_rna(a3);
                    }
                }
                uint32_t ah[4] = { __float_as_uint(a0), __float_as_uint(a1),
                                   __float_as_uint(a2), __float_as_uint(a3) };
#pragma unroll
                for (int nt = 0; nt < NTL; nt++) MMA_TF32(acc[mt][nt], ah, bh[nt]);
            }
        }
    };

    // ---- pipelined mainloop (2-stage cp.async) ----
    prefetch(0, 0);
    CP_COMMIT();
    if (NC > 1) { prefetch(1, 1); CP_COMMIT(); CP_WAIT1(); }
    else        { CP_WAIT0(); }
    __syncthreads();
#pragma unroll 1
    for (int c = 0; c < NC; c++) {
        compute(c & 1);
        __syncthreads();
        if (c + 2 < NC) {
            prefetch(c + 2, c & 1);
            CP_COMMIT();
            CP_WAIT1();
        } else if (c + 1 < NC) {
            CP_WAIT0();
        }
        __syncthreads();
    }

    // ---- epilogue straight from accumulators ----
    float lsum = 0.0f;
#pragma unroll
    for (int mt = 0; mt < 4; mt++) {
#pragma unroll
        for (int nt = 0; nt < NTL; nt++) {
            int row = bm + warp_m * 64 + mt * 16 + g;
            int col = bn + warp_n * WN + nt * 8 + 2 * t;
            float b0 = bias[col], b1 = bias[col + 1];
            float v0 = acc[mt][nt][0] + b0, v1 = acc[mt][nt][1] + b1;
            float v2 = acc[mt][nt][2] + b0, v3 = acc[mt][nt][3] + b1;
            size_t i0 = (size_t)row * N + col;
            size_t i1 = (size_t)(row + 8) * N + col;
            if (EPI == 0) {           // relu + tf32 pre-round for next encoder GEMM
                v0 = tf32_rna(fmaxf(v0, 0.0f)); v1 = tf32_rna(fmaxf(v1, 0.0f));
                v2 = tf32_rna(fmaxf(v2, 0.0f)); v3 = tf32_rna(fmaxf(v3, 0.0f));
                *reinterpret_cast<float2*>(&Cf[i0]) = make_float2(v0, v1);
                *reinterpret_cast<float2*>(&Cf[i1]) = make_float2(v2, v3);
            } else if (EPI == 1) {    // z: fp32 (cluster) + bf16 (decoder)
                *reinterpret_cast<float2*>(&Cf[i0]) = make_float2(v0, v1);
                *reinterpret_cast<float2*>(&Cf[i1]) = make_float2(v2, v3);
                *reinterpret_cast<__nv_bfloat162*>(&Cb[i0]) = __floats2bfloat162_rn(v0, v1);
                *reinterpret_cast<__nv_bfloat162*>(&Cb[i1]) = __floats2bfloat162_rn(v2, v3);
            } else if (EPI == 3) {    // decoder: relu -> bf16
                v0 = fmaxf(v0, 0.0f); v1 = fmaxf(v1, 0.0f);
                v2 = fmaxf(v2, 0.0f); v3 = fmaxf(v3, 0.0f);
                *reinterpret_cast<__nv_bfloat162*>(&Cb[i0]) = __floats2bfloat162_rn(v0, v1);
                *reinterpret_cast<__nv_bfloat162*>(&Cb[i1]) = __floats2bfloat162_rn(v2, v3);
            } else {                  // EPI == 2: fused sqdiff
                float2 x0 = *reinterpret_cast<const float2*>(&X[i0]);
                float2 x1 = *reinterpret_cast<const float2*>(&X[i1]);
                float d0 = v0 - x0.x, d1 = v1 - x0.y, d2 = v2 - x1.x, d3 = v3 - x1.y;
                lsum += d0 * d0 + d1 * d1 + d2 * d2 + d3 * d3;
            }
        }
    }
    if (EPI == 2) {
        __syncthreads();
        float* red = (float*)smem;
        red[tid] = lsum;
        __syncthreads();
        for (int s2 = 128; s2 > 0; s2 >>= 1) {
            if (tid < s2) red[tid] += red[tid + s2];
            __syncthreads();
        }
        if (tid == 0) part[blockIdx.y * gridDim.x + blockIdx.x] = red[0];
    }
}

// ---------------- clustering pass A -------------------------------------------
__global__ void cluster_pass(const float* __restrict__ t1,
                             const float* __restrict__ clu,
                             float* __restrict__ out_predict) {
    __shared__ float cs[KCLU * NZ];
    __shared__ float u_s[KCLU];
    __shared__ float red[256];
    int tid = threadIdx.x;
    for (int i = tid; i < KCLU * NZ; i += 256) cs[i] = clu[i];
    if (tid < KCLU) u_s[tid] = 0.0f;
    __syncthreads();

    int p = blockIdx.x * 256 + tid;
    float zr[NZ];
    const float* zp = g_z + (size_t)p * NZ;
#pragma unroll
    for (int i = 0; i < NZ; i++) zr[i] = zp[i];

    float cm = (t1[p * 3 + 0] * 0.01f) * (t1[p * 3 + 1] * 0.01f) * (t1[p * 3 + 2] * 0.01f)
               * 0.99f + 1.0f;
    float s = 0.0f;
#pragma unroll
    for (int i = 0; i < NZ; i++) { zr[i] *= cm; s += zr[i]; }
    float mean = s * (1.0f / NZ);
    float var = 0.0f;
#pragma unroll
    for (int i = 0; i < NZ; i++) { float d = zr[i] - mean; var += d * d; }
    float isd = 1.0f / sqrtf(var * (1.0f / (NZ - 1)));
#pragma unroll
    for (int i = 0; i < NZ; i++) zr[i] = (zr[i] - mean) * isd;

    float sumq = 0.0f, best = -1.0f, best2 = -1.0f;
    int bi = 0;
    for (int j = 0; j < KCLU; j++) {
        const float* c = &cs[j * NZ];
        float d = 0.0f;
#pragma unroll
        for (int i = 0; i < NZ; i++) { float tt = zr[i] - c[i]; d += tt * tt; }
        float qu = EPSF + d;
        sumq += qu;
        if (qu > best) { best2 = best; best = qu; bi = j; }
        else if (qu > best2) best2 = qu;
    }
    out_predict[p] = (float)bi;
    atomicAdd(&g_cnt[bi], 1);
    if (best - best2 < GAP_TAU * best) {
        int ii = atomicAdd(&g_nflag, 1);
        g_flaglist[ii] = p;
    }

    float inv = 1.0f / sumq;
    float Sl = 0.0f;
    float* qrow = g_q + (size_t)p * KCLU;
    for (int j = 0; j < KCLU; j++) {
        const float* c = &cs[j * NZ];
        float d = 0.0f;
#pragma unroll
        for (int i = 0; i < NZ; i++) { float tt = zr[i] - c[i]; d += tt * tt; }
        float qn = (EPSF + d) * inv;
        qrow[j] = qn;
        atomicAdd(&u_s[j], qn);
        float lq = logf(qn);
        float tq = (1.0f - qn) * (1.0f - qn) * lq * INDEXF;
        Sl += sqrtf(-1.0f / tq);
    }

    red[tid] = Sl;
    __syncthreads();
    for (int s2 = 128; s2 > 0; s2 >>= 1) {
        if (tid < s2) red[tid] += red[tid + s2];
        __syncthreads();
    }
    if (tid == 0) g_Spart[blockIdx.x] = red[0];
    __syncthreads();
    if (tid < KCLU) g_upart[blockIdx.x * KCLU + tid] = u_s[tid];
}

// ---------------- fp32 rescue for near-tie points ------------------------------
#define RB 8
__global__ void __launch_bounds__(256, 1)
rescue_kernel(const float* __restrict__ x, const float* __restrict__ t1,
              const float* __restrict__ clu,
              const float* __restrict__ We1, const float* __restrict__ be1,
              const float* __restrict__ We2, const float* __restrict__ be2,
              const float* __restrict__ We3, const float* __restrict__ be3,
              const float* __restrict__ Wz,  const float* __restrict__ bz,
              float* __restrict__ out_predict) {
    extern __shared__ float sm[];
    float* xb  = sm;                  // [1024][RB]
    float* hh  = xb + RB * 1024;      // [2048][RB]
    float* s1b = hh + RB * 2048;      // [512][RB]
    float* s2b = s1b + RB * 512;      // [512][RB]
    float* zz  = s2b + RB * 512;      // [RB][32]
    float* pz  = zz + RB * 32;        // [8][32][RB]
    float* dst = pz + 8 * 32 * RB;    // [128]
    const int tid = threadIdx.x;
    const int nf = g_nflag;

    for (int base = blockIdx.x * RB; base < nf; base += gridDim.x * RB) {
        const int cb = min(RB, nf - base);
        int plist[RB];
#pragma unroll
        for (int i = 0; i < RB; i++) plist[i] = g_flaglist[base + (i < cb ? i : 0)];
        __syncthreads();
        for (int k = tid; k < 1024; k += 256) {
#pragma unroll
            for (int i = 0; i < RB; i++)
                xb[k * RB + i] = x[(size_t)plist[i] * 1024 + k];
        }
        __syncthreads();
        for (int n = tid; n < 512; n += 256) {
            float acc[RB] = {};
            for (int k = 0; k < 1024; k++) {
                float w = We1[(size_t)k * 512 + n];
                float4 v0 = *reinterpret_cast<const float4*>(&xb[k * RB]);
                float4 v1 = *reinterpret_cast<const float4*>(&xb[k * RB + 4]);
                acc[0] += v0.x * w; acc[1] += v0.y * w; acc[2] += v0.z * w; acc[3] += v0.w * w;
                acc[4] += v1.x * w; acc[5] += v1.y * w; acc[6] += v1.z * w; acc[7] += v1.w * w;
            }
            float b = be1[n];
#pragma unroll
            for (int i = 0; i < RB; i++) s1b[n * RB + i] = fmaxf(acc[i] + b, 0.0f);
        }
        __syncthreads();
        for (int n = tid; n < 512; n += 256) {
            float acc[RB] = {};
            for (int k = 0; k < 512; k++) {
                float w = We2[(size_t)k * 512 + n];
                float4 v0 = *reinterpret_cast<const float4*>(&s1b[k * RB]);
                float4 v1 = *reinterpret_cast<const float4*>(&s1b[k * RB + 4]);
                acc[0] += v0.x * w; acc[1] += v0.y * w; acc[2] += v0.z * w; acc[3] += v0.w * w;
                acc[4] += v1.x * w; acc[5] += v1.y * w; acc[6] += v1.z * w; acc[7] += v1.w * w;
            }
            float b = be2[n];
#pragma unroll
            for (int i = 0; i < RB; i++) s2b[n * RB + i] = fmaxf(acc[i] + b, 0.0f);
        }
        __syncthreads();
        for (int n = tid; n < 2048; n += 256) {
            float acc[RB] = {};
            for (int k = 0; k < 512; k++) {
                float w = We3[(size_t)k * 2048 + n];
                float4 v0 = *reinterpret_cast<const float4*>(&s2b[k * RB]);
                float4 v1 = *reinterpret_cast<const float4*>(&s2b[k * RB + 4]);
                acc[0] += v0.x * w; acc[1] += v0.y * w; acc[2] += v0.z * w; acc[3] += v0.w * w;
                acc[4] += v1.x * w; acc[5] += v1.y * w; acc[6] += v1.z * w; acc[7] += v1.w * w;
            }
            float b = be3[n];
#pragma unroll
            for (int i = 0; i < RB; i++) hh[n * RB + i] = fmaxf(acc[i] + b, 0.0f);
        }
        __syncthreads();
        {
            int n = tid & 31, kc = tid >> 5;
            float acc[RB] = {};
            for (int k = kc * 256; k < kc * 256 + 256; k++) {
                float w = Wz[(size_t)k * 32 + n];
                float4 v0 = *reinterpret_cast<const float4*>(&hh[k * RB]);
                float4 v1 = *reinterpret_cast<const float4*>(&hh[k * RB + 4]);
                acc[0] += v0.x * w; acc[1] += v0.y * w; acc[2] += v0.z * w; acc[3] += v0.w * w;
                acc[4] += v1.x * w; acc[5] += v1.y * w; acc[6] += v1.z * w; acc[7] += v1.w * w;
            }
#pragma unroll
            for (int i = 0; i < RB; i++) pz[(kc * 32 + n) * RB + i] = acc[i];
        }
        __syncthreads();
        if (tid < 32) {
            int n = tid;
            float b = bz[n];
#pragma unroll
            for (int i = 0; i < RB; i++) {
                float s = 0.0f;
                for (int kc = 0; kc < 8; kc++) s += pz[(kc * 32 + n) * RB + i];
                zz[i * 32 + n] = s + b;
            }
        }
        __syncthreads();
        if (tid < cb) {
            int i = tid;
            int p = plist[i];
            float cm = (t1[p * 3 + 0] * 0.01f) * (t1[p * 3 + 1] * 0.01f) *
                       (t1[p * 3 + 2] * 0.01f) * 0.99f + 1.0f;
            float s = 0.0f;
            for (int k = 0; k < NZ; k++) { zz[i * 32 + k] *= cm; s += zz[i * 32 + k]; }
            float mean = s * (1.0f / NZ);
            float var = 0.0f;
            for (int k = 0; k < NZ; k++) { float d = zz[i * 32 + k] - mean; var += d * d; }
            float isd = 1.0f / sqrtf(var * (1.0f / (NZ - 1)));
            for (int k = 0; k < NZ; k++) zz[i * 32 + k] = (zz[i * 32 + k] - mean) * isd;
        }
        __syncthreads();
        for (int i = 0; i < cb; i++) {
            if (tid < KCLU) {
                float d = 0.0f;
                for (int k = 0; k < NZ; k++) {
                    float tt = zz[i * 32 + k] - clu[tid * NZ + k];
                    d += tt * tt;
                }
                dst[tid] = d;
            }
            __syncthreads();
            if (tid == 0) {
                float best = -1.0f; int bi = 0;
                for (int j = 0; j < KCLU; j++)
                    if (dst[j] > best) { best = dst[j]; bi = j; }
                int p = plist[i];
                int old = (int)out_predict[p];
                if (old != bi) {
                    atomicAdd(&g_cnt[old], -1);
                    atomicAdd(&g_cnt[bi], 1);
                    out_predict[p] = (float)bi;
                }
            }
            __syncthreads();
        }
    }
}

// ---------------- stats pass B -------------------------------------------------
__global__ void stats_kernel() {
    __shared__ float u[KCLU];
    __shared__ float sred[128];
    int tid = threadIdx.x;
    if (tid < KCLU) {
        float s = 0.0f;
        for (int b = 0; b < NBLK_PTS; b++) s += g_upart[b * KCLU + tid];
        u[tid] = s;
    }
    float sp = (tid < NBLK_PTS) ? g_Spart[tid] : 0.0f;
    sred[tid] = sp;
    __syncthreads();
    for (int s = 64; s > 0; s >>= 1) {
        if (tid < s) sred[tid] += sred[tid + s];
        __syncthreads();
    }
    if (tid == 0) {
        float S = sred[0];
        float um = 0.0f;
        for (int j = 0; j < KCLU; j++) um += u[j];
        um /= KCLU;
        float uv = 0.0f;
        for (int j = 0; j < KCLU; j++) { float d = u[j] - um; uv += d * d; }
        float usd = sqrtf(uv / (KCLU - 1));

        float v[KCLU];
        float vm = 0.0f;
        for (int j = 0; j < KCLU; j++) {
            int c = g_cnt[j]; if (c < 1) c = 1;
            v[j] = sqrtf((float)c) * S;
            vm += v[j];
        }
        vm /= KCLU;
        float vv = 0.0f;
        for (int j = 0; j < KCLU; j++) { float d = v[j] - vm; vv += d * d; }
        float vsd = sqrtf(vv / (KCLU - 1));

        float umin = 1e30f, vmin = 1e30f;
        for (int j = 0; j < KCLU; j++) {
            float un = (u[j] - um) / usd;
            float vn = (v[j] - vm) / vsd;
            u[j] = un; v[j] = vn;
            if (un < umin) umin = un;
            if (vn < vmin) vmin = vn;
        }
        for (int j = 0; j < KCLU; j++)
            g_f[j] = (u[j] - umin + 0.001f) + (v[j] - vmin + 0.001f) + 1.0f;
    }
}

// ---------------- KL pass C -----------------------------------------------------
__global__ void kl_pass() {
    __shared__ float fs[KCLU];
    __shared__ float red[256];
    int tid = threadIdx.x;
    if (tid < KCLU) fs[tid] = g_f[tid];
    __syncthreads();
    int p = blockIdx.x * 256 + tid;
    const float* qrow = g_q + (size_t)p * KCLU;
    float sw = 0.0f;
    for (int j = 0; j < KCLU; j++) { float q = qrow[j]; sw += q * q / fs[j]; }
    float inv = 1.0f / sw;
    float kl = 0.0f;
    for (int j = 0; j < KCLU; j++) {
        float q = qrow[j];
        float pj = q * q / fs[j] * inv;
        kl += pj * (logf(pj) - logf(q));
    }
    red[tid] = kl;
    __syncthreads();
    for (int s2 = 128; s2 > 0; s2 >>= 1) {
        if (tid < s2) red[tid] += red[tid + s2];
        __syncthreads();
    }
    if (tid == 0) g_klpart[blockIdx.x] = red[0];
}

// ---------------- final loss ----------------------------------------------------
__global__ void final_kernel(const float* __restrict__ clu, float* __restrict__ out) {
    __shared__ float red[256];
    int tid = threadIdx.x;
    float kl = 0.0f;
    for (int i = tid; i < NBLK_PTS; i += 256) kl += g_klpart[i];
    float re = 0.0f;
    for (int i = tid; i < NBLK_RE; i += 256) re += g_repart[i];
    float D = 0.0f;
    for (int idx = tid; idx < KCLU * KCLU; idx += 256) {
        int i = idx / KCLU, j = idx % KCLU;
        float d = 0.0f;
        for (int kk = 0; kk < NZ; kk++) {
            float t = clu[i * NZ + kk] - clu[j * NZ + kk];
            d += t * t;
        }
        D += d;
    }
    red[tid] = kl; __syncthreads();
    for (int s = 128; s > 0; s >>= 1) { if (tid < s) red[tid] += red[tid + s]; __syncthreads(); }
    float kls = red[0]; __syncthreads();
    red[tid] = re; __syncthreads();
    for (int s = 128; s > 0; s >>= 1) { if (tid < s) red[tid] += red[tid + s]; __syncthreads(); }
    float res = red[0]; __syncthreads();
    red[tid] = D; __syncthreads();
    for (int s = 128; s > 0; s >>= 1) { if (tid < s) red[tid] += red[tid + s]; __syncthreads(); }
    if (tid == 0) {
        float kl_loss = 0.01f * kls / ((float)N_PTS * (float)KCLU);
        float re_loss = res / ((float)N_PTS * 1024.0f);
        float mean_d = red[0] / (float)(KCLU * KCLU - KCLU);
        out[N_PTS] = kl_loss + re_loss + 0.01f / mean_d;
    }
}

// ---------------- host ----------------------------------------------------------
extern "C" void kernel_launch(void* const* d_in, const int* in_sizes, int n_in,
                              void* d_out, int out_size) {
    const float* x   = (const float*)d_in[0];
    const float* t1  = (const float*)d_in[1];
    const float* clu = (const float*)d_in[2];
    const float* We1 = (const float*)d_in[3];  const float* be1 = (const float*)d_in[4];
    const float* We2 = (const float*)d_in[5];  const float* be2 = (const float*)d_in[6];
    const float* We3 = (const float*)d_in[7];  const float* be3 = (const float*)d_in[8];
    const float* Wz  = (const float*)d_in[9];  const float* bz  = (const float*)d_in[10];
    const float* Wd1 = (const float*)d_in[11]; const float* bd1 = (const float*)d_in[12];
    const float* Wd2 = (const float*)d_in[13]; const float* bd2 = (const float*)d_in[14];
    const float* Wd3 = (const float*)d_in[15]; const float* bd3 = (const float*)d_in[16];
    const float* Wxb = (const float*)d_in[17]; const float* bxb = (const float*)d_in[18];
    float* out = (float*)d_out;

    float *P, *h1, *h2, *zf, *wr, *repart;
    __nv_bfloat16 *zbh, *d1b, *d2b, *d3b;
    cudaGetSymbolAddress((void**)&P,   g_P);
    cudaGetSymbolAddress((void**)&h1,  g_h1);
    cudaGetSymbolAddress((void**)&h2,  g_h2);
    cudaGetSymbolAddress((void**)&zf,  g_z);
    cudaGetSymbolAddress((void**)&zbh, g_zbh);
    cudaGetSymbolAddress((void**)&d1b, g_d1b);
    cudaGetSymbolAddress((void**)&d2b, g_d2b);
    cudaGetSymbolAddress((void**)&d3b, g_d3b);
    cudaGetSymbolAddress((void**)&wr,  g_wr);
    cudaGetSymbolAddress((void**)&repart, g_repart);

    constexpr int SM_F32 = (128 * 32 * 4 + 32 * 136 * 4) * 2;   // 67584 B
    constexpr int SM_Z   = (128 * 32 * 4 + 32 * 40 * 4) * 2;    // 43008 B
    constexpr int SM_BF  = (128 * 40 * 2 + 32 * 136 * 4) * 2;   // 55296 B
    constexpr int SM_RES = (RB * 1024 + RB * 2048 + RB * 512 + RB * 512 + RB * 32
                            + 8 * 32 * RB + 128) * 4;
    cudaFuncSetAttribute(mma_gemm<128, 0, 0>, cudaFuncAttributeMaxDynamicSharedMemorySize, SM_F32);
    cudaFuncSetAttribute(mma_gemm<128, 1, 0>, cudaFuncAttributeMaxDynamicSharedMemorySize, SM_F32);
    cudaFuncSetAttribute(mma_gemm<32, 1, 1>,  cudaFuncAttributeMaxDynamicSharedMemorySize, SM_Z);
    cudaFuncSetAttribute(mma_gemm<128, 2, 3>, cudaFuncAttributeMaxDynamicSharedMemorySize, SM_BF);
    cudaFuncSetAttribute(mma_gemm<128, 2, 2>, cudaFuncAttributeMaxDynamicSharedMemorySize, SM_BF);
    cudaFuncSetAttribute(rescue_kernel, cudaFuncAttributeMaxDynamicSharedMemorySize, SM_RES);

    init_kernel<<<1, 128>>>();

    // pre-round all weights to tf32
    auto R4 = [&](const float* w, int off, int n) {
        round4_kernel<<<(n / 4 + 255) / 256, 256>>>(
            (const float4*)w, (float4*)(wr + off), n / 4);
    };
    R4(We1, OFF_WE1, 1024 * 512);
    R4(We2, OFF_WE2, 512 * 512);
    R4(We3, OFF_WE3, 512 * 2048);
    R4(Wz,  OFF_WZ,  2048 * 32);
    R4(Wd1, OFF_WD1, 32 * 2048);
    R4(Wd2, OFF_WD2, 2048 * 512);
    R4(Wd3, OFF_WD3, 512 * 512);
    R4(Wxb, OFF_WXB, 512 * 1024);

    const dim3 blk(256);
    const int MB = N_PTS / 128;  // 232

    // encoder (tf32, fp32 activations — precision path for predict)
    mma_gemm<128, 0, 0><<<dim3(4, MB), blk, SM_F32>>>(x, wr + OFF_WE1, be1, h1, nullptr, nullptr, nullptr, 512, 1024);
    mma_gemm<128, 1, 0><<<dim3(4, MB), blk, SM_F32>>>(h1, wr + OFF_WE2, be2, h2, nullptr, nullptr, nullptr, 512, 512);
    mma_gemm<128, 1, 0><<<dim3(16, MB), blk, SM_F32>>>(h2, wr + OFF_WE3, be3, P, nullptr, nullptr, nullptr, 2048, 512);
    mma_gemm<32, 1, 1><<<dim3(1, MB), blk, SM_Z>>>(P, wr + OFF_WZ, bz, zf, zbh, nullptr, nullptr, 32, 2048);
    // decoder (tf32 MMA, bf16 activations — feeds only re_loss)
    mma_gemm<128, 2, 3><<<dim3(16, MB), blk, SM_BF>>>(zbh, wr + OFF_WD1, bd1, nullptr, d1b, nullptr, nullptr, 2048, 32);
    mma_gemm<128, 2, 3><<<dim3(4, MB), blk, SM_BF>>>(d1b, wr + OFF_WD2, bd2, nullptr, d2b, nullptr, nullptr, 512, 2048);
    mma_gemm<128, 2, 3><<<dim3(4, MB), blk, SM_BF>>>(d2b, wr + OFF_WD3, bd3, nullptr, d3b, nullptr, nullptr, 512, 512);
    mma_gemm<128, 2, 2><<<dim3(8, MB), blk, SM_BF>>>(d3b, wr + OFF_WXB, bxb, nullptr, nullptr, x, repart, 1024, 512);

    // clustering + rescue + loss
    cluster_pass<<<NBLK_PTS, 256>>>(t1, clu, out);
    rescue_kernel<<<148, 256, SM_RES>>>(x, t1, clu, We1, be1, We2, be2, We3, be3, Wz, bz, out);
    stats_kernel<<<1, 128>>>();
    kl_pass<<<NBLK_PTS, 256>>>();
    final_kernel<<<1, 256>>>(clu, out);

    int extra = out_size - (N_PTS + 1);
    if (extra > 0) fill_zero_kernel<<<(extra + 255) / 256, 256>>>(out + N_PTS + 1, extra);
}